// round 1
// baseline (speedup 1.0000x reference)
#include <cuda_runtime.h>
#include <cuda_bf16.h>

// Problem constants (fixed by the reference setup)
#define Bn 2
#define Pn 1024
#define Hn 128
#define Wn 128
#define NPIX (Hn * Wn)          // 16384
#define RENDER_TPB 128

// ---------------------------------------------------------------------------
// Scratch (device globals — no allocations allowed)
// ---------------------------------------------------------------------------
__device__ float4 g_a0[Bn * Pn];   // px, py, conA, conB          (unsorted)
__device__ float4 g_a1[Bn * Pn];   // conC, op(0 if invalid), 1/dep, pad
__device__ float4 g_a2[Bn * Pn];   // rgb0, rgb1, rgb2, pad
__device__ float4 g_s0[Bn * Pn];   // depth-sorted versions
__device__ float4 g_s1[Bn * Pn];
__device__ float4 g_s2[Bn * Pn];
__device__ float  g_depth[Bn * Pn];

// SH constants
#define SH_C0 0.28209479177387814f
#define SH_C1 0.4886025119029199f
#define SH_C2_0 1.0925484305920792f
#define SH_C2_1 (-1.0925484305920792f)
#define SH_C2_2 0.31539156525252005f
#define SH_C2_3 (-1.0925484305920792f)
#define SH_C2_4 0.5462742152960396f
#define SH_C3_0 (-0.5900435899266435f)
#define SH_C3_1 2.890611442640554f
#define SH_C3_2 (-0.4570457994644658f)
#define SH_C3_3 0.3731763325901154f
#define SH_C3_4 (-0.4570457994644658f)
#define SH_C3_5 1.445305721320277f
#define SH_C3_6 (-0.5900435899266435f)

// ---------------------------------------------------------------------------
// Kernel 1: per-(camera, gaussian) preprocess.  grid = (Bn), block = (Pn)
// ---------------------------------------------------------------------------
__global__ void preprocess_kernel(
    const float* __restrict__ means,      // (P,3)
    const float* __restrict__ opac,       // (P,1)
    const float* __restrict__ scales,     // (P,3)
    const float* __restrict__ rots,       // (P,4)
    const float* __restrict__ sh,         // (P,16,3)
    const float* __restrict__ viewm,      // (B,4,4) row-major
    const float* __restrict__ projm,      // (B,4,4)
    const float* __restrict__ campos,     // (B,3)
    const float* __restrict__ tanxs,      // (B)
    const float* __restrict__ tanys,      // (B)
    float* __restrict__ out_radii)        // (B,P) as float
{
    const int b = blockIdx.x;
    const int p = threadIdx.x;
    const float* V  = viewm + b * 16;
    const float* PM = projm + b * 16;
    const float tanx = tanxs[b], tany = tanys[b];

    const float mx = means[p * 3 + 0];
    const float my = means[p * 3 + 1];
    const float mz = means[p * 3 + 2];

    // t = [m,1] @ V  (row-vector * matrix)
    const float tx  = mx * V[0] + my * V[4] + mz * V[8]  + V[12];
    const float ty  = mx * V[1] + my * V[5] + mz * V[9]  + V[13];
    const float tzv = mx * V[2] + my * V[6] + mz * V[10] + V[14];

    // projection
    const float pp0 = mx * PM[0] + my * PM[4] + mz * PM[8]  + PM[12];
    const float pp1 = mx * PM[1] + my * PM[5] + mz * PM[9]  + PM[13];
    const float pp3 = mx * PM[3] + my * PM[7] + mz * PM[11] + PM[15];
    const float inw = 1.0f / (pp3 + 1e-7f);
    const float ndx = pp0 * inw, ndy = pp1 * inw;

    const float depth = tzv;
    const float fx = (float)Wn / (2.0f * tanx);
    const float fy = (float)Hn / (2.0f * tany);
    const float tz = fmaxf(depth, 1e-6f);
    const float lx = 1.3f * tanx, ly = 1.3f * tany;
    const float txc = fminf(fmaxf(tx / tz, -lx), lx) * tz;
    const float tyc = fminf(fmaxf(ty / tz, -ly), ly) * tz;

    const float J00 = fx / tz, J02 = -fx * txc / (tz * tz);
    const float J11 = fy / tz, J12 = -fy * tyc / (tz * tz);

    // T2 = J @ W^T, where W = V[:3,:3]; Wr[k][c] = V[c*4+k]
    float T2r0[3], T2r1[3];
    #pragma unroll
    for (int c = 0; c < 3; c++) {
        T2r0[c] = J00 * V[c * 4 + 0] + J02 * V[c * 4 + 2];
        T2r1[c] = J11 * V[c * 4 + 1] + J12 * V[c * 4 + 2];
    }

    // quaternion -> rotation
    float q0 = rots[p * 4 + 0], q1 = rots[p * 4 + 1];
    float q2 = rots[p * 4 + 2], q3 = rots[p * 4 + 3];
    const float qn = rsqrtf(q0 * q0 + q1 * q1 + q2 * q2 + q3 * q3);
    q0 *= qn; q1 *= qn; q2 *= qn; q3 *= qn;
    const float r = q0, qx = q1, qy = q2, qz = q3;
    float R[3][3];
    R[0][0] = 1.f - 2.f * (qy * qy + qz * qz);
    R[0][1] = 2.f * (qx * qy - r * qz);
    R[0][2] = 2.f * (qx * qz + r * qy);
    R[1][0] = 2.f * (qx * qy + r * qz);
    R[1][1] = 1.f - 2.f * (qx * qx + qz * qz);
    R[1][2] = 2.f * (qy * qz - r * qx);
    R[2][0] = 2.f * (qx * qz - r * qy);
    R[2][1] = 2.f * (qy * qz + r * qx);
    R[2][2] = 1.f - 2.f * (qx * qx + qy * qy);

    const float s0 = scales[p * 3 + 0];
    const float s1 = scales[p * 3 + 1];
    const float s2v = scales[p * 3 + 2];
    const float sq[3] = { s0 * s0, s1 * s1, s2v * s2v };

    // Sigma = R diag(sq) R^T
    float Sig[3][3];
    #pragma unroll
    for (int i = 0; i < 3; i++)
        #pragma unroll
        for (int k = 0; k < 3; k++)
            Sig[i][k] = R[i][0] * sq[0] * R[k][0]
                      + R[i][1] * sq[1] * R[k][1]
                      + R[i][2] * sq[2] * R[k][2];

    // cov2d = T2 Sigma T2^T
    float M0[3], M1[3];
    #pragma unroll
    for (int k = 0; k < 3; k++) {
        M0[k] = T2r0[0] * Sig[0][k] + T2r0[1] * Sig[1][k] + T2r0[2] * Sig[2][k];
        M1[k] = T2r1[0] * Sig[0][k] + T2r1[1] * Sig[1][k] + T2r1[2] * Sig[2][k];
    }
    const float cov00 = M0[0] * T2r0[0] + M0[1] * T2r0[1] + M0[2] * T2r0[2];
    const float cov01 = M0[0] * T2r1[0] + M0[1] * T2r1[1] + M0[2] * T2r1[2];
    const float cov11 = M1[0] * T2r1[0] + M1[1] * T2r1[1] + M1[2] * T2r1[2];

    const float a  = cov00 + 0.3f;
    const float cc = cov11 + 0.3f;
    const float bb = cov01;
    const float det = a * cc - bb * bb;
    const bool valid = (det > 0.0f) && (depth > 0.2f);
    const float dets = valid ? det : 1.0f;
    const float conA =  cc / dets;
    const float conB = -bb / dets;
    const float conC =  a  / dets;
    const float mid = 0.5f * (a + cc);
    const float lam = mid + sqrtf(fmaxf(0.1f, mid * mid - det));
    const float radf = valid ? ceilf(3.0f * sqrtf(lam)) : 0.0f;

    const float px = ((ndx + 1.0f) * (float)Wn - 1.0f) * 0.5f;
    const float py = ((ndy + 1.0f) * (float)Hn - 1.0f) * 0.5f;

    // SH -> rgb
    const float dx0 = mx - campos[b * 3 + 0];
    const float dy0 = my - campos[b * 3 + 1];
    const float dz0 = mz - campos[b * 3 + 2];
    const float dinv = rsqrtf(dx0 * dx0 + dy0 * dy0 + dz0 * dz0);
    const float x = dx0 * dinv, y = dy0 * dinv, z = dz0 * dinv;
    const float xx = x * x, yy = y * y, zz = z * z;
    const float xy = x * y, yz = y * z, xz = x * z;
    float basis[16];
    basis[0]  = SH_C0;
    basis[1]  = -SH_C1 * y;
    basis[2]  =  SH_C1 * z;
    basis[3]  = -SH_C1 * x;
    basis[4]  = SH_C2_0 * xy;
    basis[5]  = SH_C2_1 * yz;
    basis[6]  = SH_C2_2 * (2.0f * zz - xx - yy);
    basis[7]  = SH_C2_3 * xz;
    basis[8]  = SH_C2_4 * (xx - yy);
    basis[9]  = SH_C3_0 * y * (3.0f * xx - yy);
    basis[10] = SH_C3_1 * xy * z;
    basis[11] = SH_C3_2 * y * (4.0f * zz - xx - yy);
    basis[12] = SH_C3_3 * z * (2.0f * zz - 3.0f * xx - 3.0f * yy);
    basis[13] = SH_C3_4 * x * (4.0f * zz - xx - yy);
    basis[14] = SH_C3_5 * z * (xx - yy);
    basis[15] = SH_C3_6 * x * (xx - 3.0f * yy);

    float rgb[3];
    #pragma unroll
    for (int c = 0; c < 3; c++) {
        float res = 0.0f;
        #pragma unroll
        for (int k = 0; k < 16; k++)
            res += basis[k] * sh[p * 48 + k * 3 + c];
        rgb[c] = fmaxf(res + 0.5f, 0.0f);
    }

    const float op = valid ? opac[p] : 0.0f;
    const float invdep = 1.0f / tz;

    const int gi = b * Pn + p;
    g_a0[gi] = make_float4(px, py, conA, conB);
    g_a1[gi] = make_float4(conC, op, invdep, 0.0f);
    g_a2[gi] = make_float4(rgb[0], rgb[1], rgb[2], 0.0f);
    g_depth[gi] = depth;
    out_radii[b * Pn + p] = radf;   // int32 values, numeric-cast to float
}

// ---------------------------------------------------------------------------
// Kernel 2: per-camera bitonic depth sort + gather into packed sorted arrays.
// grid = (Bn), block = (Pn)
// ---------------------------------------------------------------------------
__global__ void sort_gather_kernel()
{
    __shared__ float key[Pn];
    __shared__ int   idx[Pn];
    const int b = blockIdx.x;
    const int t = threadIdx.x;
    key[t] = g_depth[b * Pn + t];
    idx[t] = t;
    __syncthreads();

    for (int k = 2; k <= Pn; k <<= 1) {
        for (int j = k >> 1; j > 0; j >>= 1) {
            const int ixj = t ^ j;
            if (ixj > t) {
                const bool up = ((t & k) == 0);
                const float ka = key[t], kb = key[ixj];
                if ((ka > kb) == up) {
                    key[t] = kb; key[ixj] = ka;
                    const int ti = idx[t]; idx[t] = idx[ixj]; idx[ixj] = ti;
                }
            }
            __syncthreads();
        }
    }
    const int src = b * Pn + idx[t];
    const int dst = b * Pn + t;
    g_s0[dst] = g_a0[src];
    g_s1[dst] = g_a1[src];
    g_s2[dst] = g_a2[src];
}

// ---------------------------------------------------------------------------
// Kernel 3: render. One thread per pixel; all P gaussians in depth order,
// staged through shared memory in chunks of RENDER_TPB.
// grid = (Bn*NPIX/RENDER_TPB), block = (RENDER_TPB)
// ---------------------------------------------------------------------------
__global__ __launch_bounds__(RENDER_TPB) void render_kernel(
    const float* __restrict__ bg, float* __restrict__ out)
{
    __shared__ float4 s0[RENDER_TPB], s1[RENDER_TPB], s2[RENDER_TPB];

    const int gpix = blockIdx.x * RENDER_TPB + threadIdx.x;
    const int b = gpix >> 14;            // / NPIX
    const int pix = gpix & (NPIX - 1);
    const float xf = (float)(pix & (Wn - 1));
    const float yf = (float)(pix >> 7);

    float T = 1.0f, c0 = 0.0f, c1 = 0.0f, c2 = 0.0f, ivd = 0.0f;

    for (int base = 0; base < Pn; base += RENDER_TPB) {
        const int li = base + threadIdx.x;
        s0[threadIdx.x] = g_s0[b * Pn + li];
        s1[threadIdx.x] = g_s1[b * Pn + li];
        s2[threadIdx.x] = g_s2[b * Pn + li];
        __syncthreads();

        #pragma unroll 4
        for (int j = 0; j < RENDER_TPB; j++) {
            const float4 a0 = s0[j];
            const float4 a1 = s1[j];
            const float dx = xf - a0.x;
            const float dy = yf - a0.y;
            const float power = -0.5f * (a0.z * dx * dx + a1.x * dy * dy)
                                - a0.w * dx * dy;
            const float alpha = fminf(0.99f, a1.y * __expf(power));
            if (power <= 0.0f && alpha >= (1.0f / 255.0f)) {
                const float4 a2 = s2[j];
                const float w = T * alpha;
                c0  += w * a2.x;
                c1  += w * a2.y;
                c2  += w * a2.z;
                ivd += w * a1.z;
                T *= (1.0f - alpha);
            }
        }
        __syncthreads();
    }

    const int y = pix >> 7, x = pix & (Wn - 1);
    // colors: (B,3,H,W) at offset 0
    out[((b * 3 + 0) * Hn + y) * Wn + x] = c0 + T * bg[0];
    out[((b * 3 + 1) * Hn + y) * Wn + x] = c1 + T * bg[1];
    out[((b * 3 + 2) * Hn + y) * Wn + x] = c2 + T * bg[2];
    // invdepth: (B,1,H,W) at offset B*3*H*W
    out[Bn * 3 * NPIX + b * NPIX + pix] = ivd;
}

// ---------------------------------------------------------------------------
extern "C" void kernel_launch(void* const* d_in, const int* in_sizes, int n_in,
                              void* d_out, int out_size)
{
    const float* means  = (const float*)d_in[0];
    const float* opac   = (const float*)d_in[1];
    const float* scales = (const float*)d_in[2];
    const float* rots   = (const float*)d_in[3];
    const float* sh     = (const float*)d_in[4];
    const float* bg     = (const float*)d_in[5];
    const float* viewm  = (const float*)d_in[6];
    const float* projm  = (const float*)d_in[7];
    const float* campos = (const float*)d_in[8];
    const float* tanxs  = (const float*)d_in[9];
    const float* tanys  = (const float*)d_in[10];
    float* out = (float*)d_out;

    // radii live at the tail of the output buffer: after colors + invdepth
    float* out_radii = out + Bn * 4 * NPIX;   // 131072

    preprocess_kernel<<<Bn, Pn>>>(means, opac, scales, rots, sh,
                                  viewm, projm, campos, tanxs, tanys, out_radii);
    sort_gather_kernel<<<Bn, Pn>>>();
    render_kernel<<<(Bn * NPIX) / RENDER_TPB, RENDER_TPB>>>(bg, out);
}

// round 2
// speedup vs baseline: 1.1978x; 1.1978x over previous
#include <cuda_runtime.h>
#include <cuda_bf16.h>

// Problem constants (fixed by the reference setup)
#define Bn 2
#define Pn 1024
#define Hn 128
#define Wn 128
#define NPIX (Hn * Wn)          // 16384
#define RENDER_TPB 128
#define PRE_TPB 128

// ---------------------------------------------------------------------------
// Scratch (device globals — no allocations allowed)
// ---------------------------------------------------------------------------
__device__ float4 g_a0[Bn * Pn];   // px, py, conA, conB          (unsorted)
__device__ float4 g_a1[Bn * Pn];   // conC, op, pthr(margin), 1/dep
__device__ float4 g_a2[Bn * Pn];   // rgb0, rgb1, rgb2, pad
__device__ float4 g_s0[Bn * Pn];   // depth-sorted versions
__device__ float4 g_s1[Bn * Pn];
__device__ float4 g_s2[Bn * Pn];
__device__ float  g_depth[Bn * Pn];

// SH constants
#define SH_C0 0.28209479177387814f
#define SH_C1 0.4886025119029199f
#define SH_C2_0 1.0925484305920792f
#define SH_C2_1 (-1.0925484305920792f)
#define SH_C2_2 0.31539156525252005f
#define SH_C2_3 (-1.0925484305920792f)
#define SH_C2_4 0.5462742152960396f
#define SH_C3_0 (-0.5900435899266435f)
#define SH_C3_1 2.890611442640554f
#define SH_C3_2 (-0.4570457994644658f)
#define SH_C3_3 0.3731763325901154f
#define SH_C3_4 (-0.4570457994644658f)
#define SH_C3_5 1.445305721320277f
#define SH_C3_6 (-0.5900435899266435f)

// ---------------------------------------------------------------------------
// Kernel 1: per-(camera, gaussian) preprocess.
// grid = (Bn, Pn/PRE_TPB), block = (PRE_TPB)
// ---------------------------------------------------------------------------
__global__ __launch_bounds__(PRE_TPB) void preprocess_kernel(
    const float* __restrict__ means,      // (P,3)
    const float* __restrict__ opac,       // (P,1)
    const float* __restrict__ scales,     // (P,3)
    const float* __restrict__ rots,       // (P,4)
    const float* __restrict__ sh,         // (P,16,3)
    const float* __restrict__ viewm,      // (B,4,4) row-major
    const float* __restrict__ projm,      // (B,4,4)
    const float* __restrict__ campos,     // (B,3)
    const float* __restrict__ tanxs,      // (B)
    const float* __restrict__ tanys,      // (B)
    float* __restrict__ out_radii)        // (B,P) as float
{
    const int b = blockIdx.x;
    const int p = blockIdx.y * PRE_TPB + threadIdx.x;
    const float* V  = viewm + b * 16;
    const float* PM = projm + b * 16;
    const float tanx = tanxs[b], tany = tanys[b];

    const float mx = means[p * 3 + 0];
    const float my = means[p * 3 + 1];
    const float mz = means[p * 3 + 2];

    // t = [m,1] @ V  (row-vector * matrix)
    const float tx  = mx * V[0] + my * V[4] + mz * V[8]  + V[12];
    const float ty  = mx * V[1] + my * V[5] + mz * V[9]  + V[13];
    const float tzv = mx * V[2] + my * V[6] + mz * V[10] + V[14];

    // projection
    const float pp0 = mx * PM[0] + my * PM[4] + mz * PM[8]  + PM[12];
    const float pp1 = mx * PM[1] + my * PM[5] + mz * PM[9]  + PM[13];
    const float pp3 = mx * PM[3] + my * PM[7] + mz * PM[11] + PM[15];
    const float inw = 1.0f / (pp3 + 1e-7f);
    const float ndx = pp0 * inw, ndy = pp1 * inw;

    const float depth = tzv;
    const float fx = (float)Wn / (2.0f * tanx);
    const float fy = (float)Hn / (2.0f * tany);
    const float tz = fmaxf(depth, 1e-6f);
    const float lx = 1.3f * tanx, ly = 1.3f * tany;
    const float txc = fminf(fmaxf(tx / tz, -lx), lx) * tz;
    const float tyc = fminf(fmaxf(ty / tz, -ly), ly) * tz;

    const float J00 = fx / tz, J02 = -fx * txc / (tz * tz);
    const float J11 = fy / tz, J12 = -fy * tyc / (tz * tz);

    // T2 = J @ W^T, where W = V[:3,:3]; Wr[k][c] = V[c*4+k]
    float T2r0[3], T2r1[3];
    #pragma unroll
    for (int c = 0; c < 3; c++) {
        T2r0[c] = J00 * V[c * 4 + 0] + J02 * V[c * 4 + 2];
        T2r1[c] = J11 * V[c * 4 + 1] + J12 * V[c * 4 + 2];
    }

    // quaternion -> rotation
    const float4 q = ((const float4*)rots)[p];
    const float qn = rsqrtf(q.x * q.x + q.y * q.y + q.z * q.z + q.w * q.w);
    const float r = q.x * qn, qx = q.y * qn, qy = q.z * qn, qz = q.w * qn;
    float R[3][3];
    R[0][0] = 1.f - 2.f * (qy * qy + qz * qz);
    R[0][1] = 2.f * (qx * qy - r * qz);
    R[0][2] = 2.f * (qx * qz + r * qy);
    R[1][0] = 2.f * (qx * qy + r * qz);
    R[1][1] = 1.f - 2.f * (qx * qx + qz * qz);
    R[1][2] = 2.f * (qy * qz - r * qx);
    R[2][0] = 2.f * (qx * qz - r * qy);
    R[2][1] = 2.f * (qy * qz + r * qx);
    R[2][2] = 1.f - 2.f * (qx * qx + qy * qy);

    const float s0 = scales[p * 3 + 0];
    const float s1 = scales[p * 3 + 1];
    const float s2v = scales[p * 3 + 2];
    const float sq[3] = { s0 * s0, s1 * s1, s2v * s2v };

    // Sigma = R diag(sq) R^T
    float Sig[3][3];
    #pragma unroll
    for (int i = 0; i < 3; i++)
        #pragma unroll
        for (int k = 0; k < 3; k++)
            Sig[i][k] = R[i][0] * sq[0] * R[k][0]
                      + R[i][1] * sq[1] * R[k][1]
                      + R[i][2] * sq[2] * R[k][2];

    // cov2d = T2 Sigma T2^T
    float M0[3], M1[3];
    #pragma unroll
    for (int k = 0; k < 3; k++) {
        M0[k] = T2r0[0] * Sig[0][k] + T2r0[1] * Sig[1][k] + T2r0[2] * Sig[2][k];
        M1[k] = T2r1[0] * Sig[0][k] + T2r1[1] * Sig[1][k] + T2r1[2] * Sig[2][k];
    }
    const float cov00 = M0[0] * T2r0[0] + M0[1] * T2r0[1] + M0[2] * T2r0[2];
    const float cov01 = M0[0] * T2r1[0] + M0[1] * T2r1[1] + M0[2] * T2r1[2];
    const float cov11 = M1[0] * T2r1[0] + M1[1] * T2r1[1] + M1[2] * T2r1[2];

    const float a  = cov00 + 0.3f;
    const float cc = cov11 + 0.3f;
    const float bb = cov01;
    const float det = a * cc - bb * bb;
    const bool valid = (det > 0.0f) && (depth > 0.2f);
    const float dets = valid ? det : 1.0f;
    const float conA =  cc / dets;
    const float conB = -bb / dets;
    const float conC =  a  / dets;
    const float mid = 0.5f * (a + cc);
    const float lam = mid + sqrtf(fmaxf(0.1f, mid * mid - det));
    const float radf = valid ? ceilf(3.0f * sqrtf(lam)) : 0.0f;

    const float px = ((ndx + 1.0f) * (float)Wn - 1.0f) * 0.5f;
    const float py = ((ndy + 1.0f) * (float)Hn - 1.0f) * 0.5f;

    // SH -> rgb
    const float dx0 = mx - campos[b * 3 + 0];
    const float dy0 = my - campos[b * 3 + 1];
    const float dz0 = mz - campos[b * 3 + 2];
    const float dinv = rsqrtf(dx0 * dx0 + dy0 * dy0 + dz0 * dz0);
    const float x = dx0 * dinv, y = dy0 * dinv, z = dz0 * dinv;
    const float xx = x * x, yy = y * y, zz = z * z;
    const float xy = x * y, yz = y * z, xz = x * z;
    float basis[16];
    basis[0]  = SH_C0;
    basis[1]  = -SH_C1 * y;
    basis[2]  =  SH_C1 * z;
    basis[3]  = -SH_C1 * x;
    basis[4]  = SH_C2_0 * xy;
    basis[5]  = SH_C2_1 * yz;
    basis[6]  = SH_C2_2 * (2.0f * zz - xx - yy);
    basis[7]  = SH_C2_3 * xz;
    basis[8]  = SH_C2_4 * (xx - yy);
    basis[9]  = SH_C3_0 * y * (3.0f * xx - yy);
    basis[10] = SH_C3_1 * xy * z;
    basis[11] = SH_C3_2 * y * (4.0f * zz - xx - yy);
    basis[12] = SH_C3_3 * z * (2.0f * zz - 3.0f * xx - 3.0f * yy);
    basis[13] = SH_C3_4 * x * (4.0f * zz - xx - yy);
    basis[14] = SH_C3_5 * z * (xx - yy);
    basis[15] = SH_C3_6 * x * (xx - 3.0f * yy);

    // sh row: 48 contiguous floats = 12 float4 (192B rows => 16B aligned)
    float shv[48];
    const float4* shp = (const float4*)(sh + p * 48);
    #pragma unroll
    for (int k = 0; k < 12; k++) {
        const float4 v = shp[k];
        shv[k * 4 + 0] = v.x; shv[k * 4 + 1] = v.y;
        shv[k * 4 + 2] = v.z; shv[k * 4 + 3] = v.w;
    }
    float rgb[3];
    #pragma unroll
    for (int c = 0; c < 3; c++) {
        float res = 0.0f;
        #pragma unroll
        for (int k = 0; k < 16; k++)
            res += basis[k] * shv[k * 3 + c];
        rgb[c] = fmaxf(res + 0.5f, 0.0f);
    }

    const float op = valid ? opac[p] : 0.0f;
    const float invdep = 1.0f / tz;
    // power threshold for alpha >= 1/255 : power >= -log(255*op).
    // loosen by 1e-3 margin; exact alpha test re-done in render.
    const float pthr = -__logf(255.0f * op) - 1e-3f;   // op=0 -> +inf

    const int gi = b * Pn + p;
    g_a0[gi] = make_float4(px, py, conA, conB);
    g_a1[gi] = make_float4(conC, op, pthr, invdep);
    g_a2[gi] = make_float4(rgb[0], rgb[1], rgb[2], 0.0f);
    g_depth[gi] = depth;
    out_radii[b * Pn + p] = radf;   // int32 values, numeric-cast to float
}

// ---------------------------------------------------------------------------
// Kernel 2: rank-based depth sort + scatter (O(P^2) compares, no barriers in
// the compare loop).  grid = (Bn, Pn/PRE_TPB), block = (PRE_TPB)
// Stable: ties broken by original index, matching jnp.argsort.
// ---------------------------------------------------------------------------
__global__ __launch_bounds__(PRE_TPB) void rank_scatter_kernel()
{
    __shared__ float sd[Pn];
    const int b = blockIdx.x;
    const int i = blockIdx.y * PRE_TPB + threadIdx.x;

    for (int k = threadIdx.x; k < Pn; k += PRE_TPB)
        sd[k] = g_depth[b * Pn + k];
    __syncthreads();

    const float di = sd[i];
    int rank = 0;
    #pragma unroll 8
    for (int j = 0; j < Pn; j++) {
        const float dj = sd[j];
        rank += (dj < di) || (dj == di && j < i);
    }

    const int src = b * Pn + i;
    const int dst = b * Pn + rank;
    g_s0[dst] = g_a0[src];
    g_s1[dst] = g_a1[src];
    g_s2[dst] = g_a2[src];
}

// ---------------------------------------------------------------------------
// Kernel 3: render. One thread per pixel; all P gaussians in depth order,
// staged through shared memory in chunks of RENDER_TPB.
// Threshold precheck avoids __expf on ~99% of iterations.
// grid = (Bn*NPIX/RENDER_TPB), block = (RENDER_TPB)
// ---------------------------------------------------------------------------
__global__ __launch_bounds__(RENDER_TPB) void render_kernel(
    const float* __restrict__ bg, float* __restrict__ out)
{
    __shared__ float4 s0[RENDER_TPB], s1[RENDER_TPB], s2[RENDER_TPB];

    const int gpix = blockIdx.x * RENDER_TPB + threadIdx.x;
    const int b = gpix >> 14;            // / NPIX
    const int pix = gpix & (NPIX - 1);
    const float xf = (float)(pix & (Wn - 1));
    const float yf = (float)(pix >> 7);

    float T = 1.0f, c0 = 0.0f, c1 = 0.0f, c2 = 0.0f, ivd = 0.0f;

    for (int base = 0; base < Pn; base += RENDER_TPB) {
        const int li = base + threadIdx.x;
        s0[threadIdx.x] = g_s0[b * Pn + li];
        s1[threadIdx.x] = g_s1[b * Pn + li];
        s2[threadIdx.x] = g_s2[b * Pn + li];
        __syncthreads();

        #pragma unroll 8
        for (int j = 0; j < RENDER_TPB; j++) {
            const float4 a0 = s0[j];
            const float4 a1 = s1[j];
            const float dx = xf - a0.x;
            const float dy = yf - a0.y;
            const float power = -0.5f * (a0.z * dx * dx + a1.x * dy * dy)
                                - a0.w * dx * dy;
            // precheck: power>=pthr(margin) && power<=0 ; NaN power fails.
            if (power >= a1.z && power <= 0.0f) {
                const float alpha = fminf(0.99f, a1.y * __expf(power));
                if (alpha >= (1.0f / 255.0f)) {   // exact reference test
                    const float4 a2 = s2[j];
                    const float w = T * alpha;
                    c0  += w * a2.x;
                    c1  += w * a2.y;
                    c2  += w * a2.z;
                    ivd += w * a1.w;
                    T *= (1.0f - alpha);
                }
            }
        }
        // barrier doubles as block-uniform early exit (tail contribution < 2e-5)
        if (__syncthreads_and(T < 2e-5f)) break;
    }

    const int y = pix >> 7, x = pix & (Wn - 1);
    // colors: (B,3,H,W) at offset 0
    out[((b * 3 + 0) * Hn + y) * Wn + x] = c0 + T * bg[0];
    out[((b * 3 + 1) * Hn + y) * Wn + x] = c1 + T * bg[1];
    out[((b * 3 + 2) * Hn + y) * Wn + x] = c2 + T * bg[2];
    // invdepth: (B,1,H,W) at offset B*3*H*W
    out[Bn * 3 * NPIX + b * NPIX + pix] = ivd;
}

// ---------------------------------------------------------------------------
extern "C" void kernel_launch(void* const* d_in, const int* in_sizes, int n_in,
                              void* d_out, int out_size)
{
    const float* means  = (const float*)d_in[0];
    const float* opac   = (const float*)d_in[1];
    const float* scales = (const float*)d_in[2];
    const float* rots   = (const float*)d_in[3];
    const float* sh     = (const float*)d_in[4];
    const float* bg     = (const float*)d_in[5];
    const float* viewm  = (const float*)d_in[6];
    const float* projm  = (const float*)d_in[7];
    const float* campos = (const float*)d_in[8];
    const float* tanxs  = (const float*)d_in[9];
    const float* tanys  = (const float*)d_in[10];
    float* out = (float*)d_out;

    // radii live at the tail of the output buffer: after colors + invdepth
    float* out_radii = out + Bn * 4 * NPIX;   // 131072

    dim3 pre_grid(Bn, Pn / PRE_TPB);
    preprocess_kernel<<<pre_grid, PRE_TPB>>>(means, opac, scales, rots, sh,
                                             viewm, projm, campos, tanxs, tanys,
                                             out_radii);
    rank_scatter_kernel<<<pre_grid, PRE_TPB>>>();
    render_kernel<<<(Bn * NPIX) / RENDER_TPB, RENDER_TPB>>>(bg, out);
}

// round 3
// speedup vs baseline: 2.8199x; 2.3543x over previous
#include <cuda_runtime.h>
#include <cuda_bf16.h>

// Problem constants (fixed by the reference setup)
#define Bn 2
#define Pn 1024
#define Hn 128
#define Wn 128
#define NPIX (Hn * Wn)          // 16384
#define TILE_W 16
#define TILE_H 8
#define TILES_X (Wn / TILE_W)   // 8
#define TILES_Y (Hn / TILE_H)   // 16
#define NTILES (TILES_X * TILES_Y)  // 128 per camera
#define PRE_TPB 64

// ---------------------------------------------------------------------------
// Scratch (device globals — no allocations allowed)
// ---------------------------------------------------------------------------
__device__ float4 g_a0[Bn * Pn];    // px, py, conA, conB          (unsorted)
__device__ float4 g_a1[Bn * Pn];    // conC, op, pthr(margin), 1/dep
__device__ float4 g_a2[Bn * Pn];    // rgb0, rgb1, rgb2, pad
__device__ float4 g_bb[Bn * Pn];    // xmin, xmax, ymin, ymax (AABB of ellipse)
__device__ float4 g_s0[Bn * Pn];    // depth-sorted versions
__device__ float4 g_s1[Bn * Pn];
__device__ float4 g_s2[Bn * Pn];
__device__ float4 g_sbb[Bn * Pn];
__device__ float  g_depth[Bn * Pn];
__device__ unsigned short g_list[Bn * NTILES * Pn];  // per-tile depth-ordered lists
__device__ int    g_cnt[Bn * NTILES];

// SH constants
#define SH_C0 0.28209479177387814f
#define SH_C1 0.4886025119029199f
#define SH_C2_0 1.0925484305920792f
#define SH_C2_1 (-1.0925484305920792f)
#define SH_C2_2 0.31539156525252005f
#define SH_C2_3 (-1.0925484305920792f)
#define SH_C2_4 0.5462742152960396f
#define SH_C3_0 (-0.5900435899266435f)
#define SH_C3_1 2.890611442640554f
#define SH_C3_2 (-0.4570457994644658f)
#define SH_C3_3 0.3731763325901154f
#define SH_C3_4 (-0.4570457994644658f)
#define SH_C3_5 1.445305721320277f
#define SH_C3_6 (-0.5900435899266435f)

// ---------------------------------------------------------------------------
// Kernel 1: per-(camera, gaussian) preprocess.
// grid = (Bn, Pn/PRE_TPB), block = (PRE_TPB)
// ---------------------------------------------------------------------------
__global__ __launch_bounds__(PRE_TPB) void preprocess_kernel(
    const float* __restrict__ means,      // (P,3)
    const float* __restrict__ opac,       // (P,1)
    const float* __restrict__ scales,     // (P,3)
    const float* __restrict__ rots,       // (P,4)
    const float* __restrict__ sh,         // (P,16,3)
    const float* __restrict__ viewm,      // (B,4,4) row-major
    const float* __restrict__ projm,      // (B,4,4)
    const float* __restrict__ campos,     // (B,3)
    const float* __restrict__ tanxs,      // (B)
    const float* __restrict__ tanys,      // (B)
    float* __restrict__ out_radii)        // (B,P) as float
{
    const int b = blockIdx.x;
    const int p = blockIdx.y * PRE_TPB + threadIdx.x;
    const float* V  = viewm + b * 16;
    const float* PM = projm + b * 16;
    const float tanx = tanxs[b], tany = tanys[b];

    const float mx = means[p * 3 + 0];
    const float my = means[p * 3 + 1];
    const float mz = means[p * 3 + 2];

    // t = [m,1] @ V  (row-vector * matrix)
    const float tx  = mx * V[0] + my * V[4] + mz * V[8]  + V[12];
    const float ty  = mx * V[1] + my * V[5] + mz * V[9]  + V[13];
    const float tzv = mx * V[2] + my * V[6] + mz * V[10] + V[14];

    // projection
    const float pp0 = mx * PM[0] + my * PM[4] + mz * PM[8]  + PM[12];
    const float pp1 = mx * PM[1] + my * PM[5] + mz * PM[9]  + PM[13];
    const float pp3 = mx * PM[3] + my * PM[7] + mz * PM[11] + PM[15];
    const float inw = 1.0f / (pp3 + 1e-7f);
    const float ndx = pp0 * inw, ndy = pp1 * inw;

    const float depth = tzv;
    const float fx = (float)Wn / (2.0f * tanx);
    const float fy = (float)Hn / (2.0f * tany);
    const float tz = fmaxf(depth, 1e-6f);
    const float lx = 1.3f * tanx, ly = 1.3f * tany;
    const float txc = fminf(fmaxf(tx / tz, -lx), lx) * tz;
    const float tyc = fminf(fmaxf(ty / tz, -ly), ly) * tz;

    const float J00 = fx / tz, J02 = -fx * txc / (tz * tz);
    const float J11 = fy / tz, J12 = -fy * tyc / (tz * tz);

    // T2 = J @ W^T, where W = V[:3,:3]; Wr[k][c] = V[c*4+k]
    float T2r0[3], T2r1[3];
    #pragma unroll
    for (int c = 0; c < 3; c++) {
        T2r0[c] = J00 * V[c * 4 + 0] + J02 * V[c * 4 + 2];
        T2r1[c] = J11 * V[c * 4 + 1] + J12 * V[c * 4 + 2];
    }

    // quaternion -> rotation
    const float4 q = ((const float4*)rots)[p];
    const float qn = rsqrtf(q.x * q.x + q.y * q.y + q.z * q.z + q.w * q.w);
    const float r = q.x * qn, qx = q.y * qn, qy = q.z * qn, qz = q.w * qn;
    float R[3][3];
    R[0][0] = 1.f - 2.f * (qy * qy + qz * qz);
    R[0][1] = 2.f * (qx * qy - r * qz);
    R[0][2] = 2.f * (qx * qz + r * qy);
    R[1][0] = 2.f * (qx * qy + r * qz);
    R[1][1] = 1.f - 2.f * (qx * qx + qz * qz);
    R[1][2] = 2.f * (qy * qz - r * qx);
    R[2][0] = 2.f * (qx * qz - r * qy);
    R[2][1] = 2.f * (qy * qz + r * qx);
    R[2][2] = 1.f - 2.f * (qx * qx + qy * qy);

    const float s0 = scales[p * 3 + 0];
    const float s1 = scales[p * 3 + 1];
    const float s2v = scales[p * 3 + 2];
    const float sq[3] = { s0 * s0, s1 * s1, s2v * s2v };

    // Sigma = R diag(sq) R^T
    float Sig[3][3];
    #pragma unroll
    for (int i = 0; i < 3; i++)
        #pragma unroll
        for (int k = 0; k < 3; k++)
            Sig[i][k] = R[i][0] * sq[0] * R[k][0]
                      + R[i][1] * sq[1] * R[k][1]
                      + R[i][2] * sq[2] * R[k][2];

    // cov2d = T2 Sigma T2^T
    float M0[3], M1[3];
    #pragma unroll
    for (int k = 0; k < 3; k++) {
        M0[k] = T2r0[0] * Sig[0][k] + T2r0[1] * Sig[1][k] + T2r0[2] * Sig[2][k];
        M1[k] = T2r1[0] * Sig[0][k] + T2r1[1] * Sig[1][k] + T2r1[2] * Sig[2][k];
    }
    const float cov00 = M0[0] * T2r0[0] + M0[1] * T2r0[1] + M0[2] * T2r0[2];
    const float cov01 = M0[0] * T2r1[0] + M0[1] * T2r1[1] + M0[2] * T2r1[2];
    const float cov11 = M1[0] * T2r1[0] + M1[1] * T2r1[1] + M1[2] * T2r1[2];

    const float a  = cov00 + 0.3f;
    const float cc = cov11 + 0.3f;
    const float bb = cov01;
    const float det = a * cc - bb * bb;
    const bool valid = (det > 0.0f) && (depth > 0.2f);
    const float dets = valid ? det : 1.0f;
    const float conA =  cc / dets;
    const float conB = -bb / dets;
    const float conC =  a  / dets;
    const float mid = 0.5f * (a + cc);
    const float lam = mid + sqrtf(fmaxf(0.1f, mid * mid - det));
    const float radf = valid ? ceilf(3.0f * sqrtf(lam)) : 0.0f;

    const float px = ((ndx + 1.0f) * (float)Wn - 1.0f) * 0.5f;
    const float py = ((ndy + 1.0f) * (float)Hn - 1.0f) * 0.5f;

    // SH -> rgb
    const float dx0 = mx - campos[b * 3 + 0];
    const float dy0 = my - campos[b * 3 + 1];
    const float dz0 = mz - campos[b * 3 + 2];
    const float dinv = rsqrtf(dx0 * dx0 + dy0 * dy0 + dz0 * dz0);
    const float x = dx0 * dinv, y = dy0 * dinv, z = dz0 * dinv;
    const float xx = x * x, yy = y * y, zz = z * z;
    const float xy = x * y, yz = y * z, xz = x * z;
    float basis[16];
    basis[0]  = SH_C0;
    basis[1]  = -SH_C1 * y;
    basis[2]  =  SH_C1 * z;
    basis[3]  = -SH_C1 * x;
    basis[4]  = SH_C2_0 * xy;
    basis[5]  = SH_C2_1 * yz;
    basis[6]  = SH_C2_2 * (2.0f * zz - xx - yy);
    basis[7]  = SH_C2_3 * xz;
    basis[8]  = SH_C2_4 * (xx - yy);
    basis[9]  = SH_C3_0 * y * (3.0f * xx - yy);
    basis[10] = SH_C3_1 * xy * z;
    basis[11] = SH_C3_2 * y * (4.0f * zz - xx - yy);
    basis[12] = SH_C3_3 * z * (2.0f * zz - 3.0f * xx - 3.0f * yy);
    basis[13] = SH_C3_4 * x * (4.0f * zz - xx - yy);
    basis[14] = SH_C3_5 * z * (xx - yy);
    basis[15] = SH_C3_6 * x * (xx - 3.0f * yy);

    // sh row: 48 contiguous floats = 12 float4 (192B rows => 16B aligned)
    float shv[48];
    const float4* shp = (const float4*)(sh + p * 48);
    #pragma unroll
    for (int k = 0; k < 12; k++) {
        const float4 v = shp[k];
        shv[k * 4 + 0] = v.x; shv[k * 4 + 1] = v.y;
        shv[k * 4 + 2] = v.z; shv[k * 4 + 3] = v.w;
    }
    float rgb[3];
    #pragma unroll
    for (int c = 0; c < 3; c++) {
        float res = 0.0f;
        #pragma unroll
        for (int k = 0; k < 16; k++)
            res += basis[k] * shv[k * 3 + c];
        rgb[c] = fmaxf(res + 0.5f, 0.0f);
    }

    const float op = valid ? opac[p] : 0.0f;
    const float invdep = 1.0f / tz;
    // power threshold for alpha >= 1/255 : power >= -log(255*op).
    // loosened margin for the render precheck; exact alpha test re-done there.
    const float p0   = -logf(255.0f * op);           // accurate log; op=0 -> +inf
    const float pthr = p0 - 1e-3f;

    // Conservative AABB of the contribution ellipse {power >= p0}:
    //   |dx| <= sqrt(-2*p0*a_cov), |dy| <= sqrt(-2*p0*c_cov)
    float4 aabb;
    if (valid && op > 0.0f) {
        const float ex = sqrtf(fmaxf(0.0f, -2.0f * p0 * a)) + 0.02f;
        const float ey = sqrtf(fmaxf(0.0f, -2.0f * p0 * cc)) + 0.02f;
        aabb = make_float4(px - ex, px + ex, py - ey, py + ey);
        // NaN px/py propagates to NaN bounds -> overlap tests all false -> culled
    } else {
        aabb = make_float4(1e9f, -1e9f, 1e9f, -1e9f);   // empty
    }

    const int gi = b * Pn + p;
    g_a0[gi] = make_float4(px, py, conA, conB);
    g_a1[gi] = make_float4(conC, op, pthr, invdep);
    g_a2[gi] = make_float4(rgb[0], rgb[1], rgb[2], 0.0f);
    g_bb[gi] = aabb;
    g_depth[gi] = depth;
    out_radii[b * Pn + p] = radf;   // int32 values, numeric-cast to float
}

// ---------------------------------------------------------------------------
// Kernel 2: rank-based depth sort + scatter. 4 threads per gaussian, each
// scans 256 candidates, shuffle-reduce, sub 0 scatters.
// grid = (Bn * Pn * 4) / 128 = 64 blocks, block = 128.
// Stable: ties broken by original index, matching jnp.argsort.
// ---------------------------------------------------------------------------
__global__ __launch_bounds__(128) void rank_scatter_kernel()
{
    __shared__ float sd[Pn];
    const int b   = blockIdx.x >> 5;           // 32 blocks per camera
    const int grp = blockIdx.x & 31;
    const int gi  = grp * 32 + (threadIdx.x >> 2);   // gaussian index 0..1023
    const int sub = threadIdx.x & 3;

    for (int k = threadIdx.x; k < Pn; k += 128)
        sd[k] = g_depth[b * Pn + k];
    __syncthreads();

    const float di = sd[gi];
    int rank = 0;
    const int j0 = sub * 256;
    #pragma unroll 8
    for (int j = j0; j < j0 + 256; j++) {
        const float dj = sd[j];
        rank += (dj < di) || (dj == di && j < gi);
    }
    rank += __shfl_xor_sync(0xffffffffu, rank, 1);
    rank += __shfl_xor_sync(0xffffffffu, rank, 2);

    if (sub == 0) {
        const int src = b * Pn + gi;
        const int dst = b * Pn + rank;
        g_s0[dst]  = g_a0[src];
        g_s1[dst]  = g_a1[src];
        g_s2[dst]  = g_a2[src];
        g_sbb[dst] = g_bb[src];
    }
}

// ---------------------------------------------------------------------------
// Kernel 3: tile binning. One warp per tile; ballot-compaction preserves
// depth order. grid = Bn*NTILES/4 = 64 blocks, block = 128 (4 warps).
// ---------------------------------------------------------------------------
__global__ __launch_bounds__(128) void bin_kernel()
{
    const int w = blockIdx.x * 4 + (threadIdx.x >> 5);   // global tile slot
    const int lane = threadIdx.x & 31;
    const int b    = w >> 7;            // / NTILES
    const int tile = w & (NTILES - 1);
    const float tx0 = (float)((tile & (TILES_X - 1)) * TILE_W);
    const float ty0 = (float)((tile >> 3) * TILE_H);
    const float tx1 = tx0 + (float)(TILE_W - 1);
    const float ty1 = ty0 + (float)(TILE_H - 1);

    unsigned short* list = g_list + w * Pn;
    int cnt = 0;
    for (int base = 0; base < Pn; base += 32) {
        const int idx = base + lane;
        const float4 bb = g_sbb[b * Pn + idx];
        const bool hit = (bb.x <= tx1) && (bb.y >= tx0) &&
                         (bb.z <= ty1) && (bb.w >= ty0);
        const unsigned mask = __ballot_sync(0xffffffffu, hit);
        if (hit) {
            const int pos = cnt + __popc(mask & ((1u << lane) - 1u));
            list[pos] = (unsigned short)idx;
        }
        cnt += __popc(mask);
    }
    if (lane == 0) g_cnt[w] = cnt;
}

// ---------------------------------------------------------------------------
// Kernel 4: render. One block per tile (16x8 = 128 threads), loop over the
// tile's depth-ordered list, staged through shared memory.
// grid = Bn*NTILES = 256, block = 128.
// ---------------------------------------------------------------------------
__global__ __launch_bounds__(128) void render_kernel(
    const float* __restrict__ bg, float* __restrict__ out)
{
    __shared__ float4 s0[128], s1[128], s2[128];

    const int w = blockIdx.x;
    const int b    = w >> 7;
    const int tile = w & (NTILES - 1);
    const int tx0 = (tile & (TILES_X - 1)) * TILE_W;
    const int ty0 = (tile >> 3) * TILE_H;
    const int xl = threadIdx.x & (TILE_W - 1);
    const int yl = threadIdx.x >> 4;
    const int x = tx0 + xl, y = ty0 + yl;
    const float xf = (float)x, yf = (float)y;

    const int cnt = g_cnt[w];
    const unsigned short* list = g_list + w * Pn;

    float T = 1.0f, c0 = 0.0f, c1 = 0.0f, c2 = 0.0f, ivd = 0.0f;

    for (int base = 0; base < cnt; base += 128) {
        const int t = base + (int)threadIdx.x;
        if (t < cnt) {
            const int li = b * Pn + (int)list[t];
            s0[threadIdx.x] = g_s0[li];
            s1[threadIdx.x] = g_s1[li];
            s2[threadIdx.x] = g_s2[li];
        }
        __syncthreads();

        const int m = min(128, cnt - base);
        for (int j = 0; j < m; j++) {
            const float4 a0 = s0[j];
            const float4 a1 = s1[j];
            const float dx = xf - a0.x;
            const float dy = yf - a0.y;
            const float power = -0.5f * (a0.z * dx * dx + a1.x * dy * dy)
                                - a0.w * dx * dy;
            // precheck: power>=pthr(margin) && power<=0 ; NaN power fails.
            if (power >= a1.z && power <= 0.0f) {
                const float alpha = fminf(0.99f, a1.y * __expf(power));
                if (alpha >= (1.0f / 255.0f)) {   // exact reference test
                    const float4 a2 = s2[j];
                    const float wgt = T * alpha;
                    c0  += wgt * a2.x;
                    c1  += wgt * a2.y;
                    c2  += wgt * a2.z;
                    ivd += wgt * a1.w;
                    T *= (1.0f - alpha);
                }
            }
        }
        if (base + 128 < cnt) {
            if (__syncthreads_and(T < 2e-5f)) break;
        }
    }

    // colors: (B,3,H,W) at offset 0
    out[((b * 3 + 0) * Hn + y) * Wn + x] = c0 + T * bg[0];
    out[((b * 3 + 1) * Hn + y) * Wn + x] = c1 + T * bg[1];
    out[((b * 3 + 2) * Hn + y) * Wn + x] = c2 + T * bg[2];
    // invdepth: (B,1,H,W) at offset B*3*H*W
    out[Bn * 3 * NPIX + b * NPIX + y * Wn + x] = ivd;
}

// ---------------------------------------------------------------------------
extern "C" void kernel_launch(void* const* d_in, const int* in_sizes, int n_in,
                              void* d_out, int out_size)
{
    const float* means  = (const float*)d_in[0];
    const float* opac   = (const float*)d_in[1];
    const float* scales = (const float*)d_in[2];
    const float* rots   = (const float*)d_in[3];
    const float* sh     = (const float*)d_in[4];
    const float* bg     = (const float*)d_in[5];
    const float* viewm  = (const float*)d_in[6];
    const float* projm  = (const float*)d_in[7];
    const float* campos = (const float*)d_in[8];
    const float* tanxs  = (const float*)d_in[9];
    const float* tanys  = (const float*)d_in[10];
    float* out = (float*)d_out;

    // radii live at the tail of the output buffer: after colors + invdepth
    float* out_radii = out + Bn * 4 * NPIX;   // 131072

    dim3 pre_grid(Bn, Pn / PRE_TPB);
    preprocess_kernel<<<pre_grid, PRE_TPB>>>(means, opac, scales, rots, sh,
                                             viewm, projm, campos, tanxs, tanys,
                                             out_radii);
    rank_scatter_kernel<<<Bn * 32, 128>>>();
    bin_kernel<<<Bn * NTILES / 4, 128>>>();
    render_kernel<<<Bn * NTILES, 128>>>(bg, out);
}